// round 2
// baseline (speedup 1.0000x reference)
#include <cuda_runtime.h>

// ---------------------------------------------------------------------------
// VanillaLSTM on GB300: persistent fp32 LSTM with f32x2 packed FMA.
// B=8192, T=128, Din=2, E=128, C=128, G=4C=512, Dout=5.
//
// Pipeline:
//   k_moments: per-t moments of the 2 input channels (for analytic input BN)
//   k_prep:    input-BN affine coeffs, fused weight transpose, fused bias
//   k_lstm:    persistent kernel: 128 CTAs x 64 rows; per step fused
//              xbn -> gates GEMM (fma.rn.f32x2) -> LSTM cell -> y=h@Woutt
//   k_final:   output BN (batch stats) + ReLU + transpose to [B,T,5]
// ---------------------------------------------------------------------------

#define BB    8192
#define TT    128
#define EE    128
#define CC    128
#define GG    512
#define DOUT  5
#define KTOT  256       // E + C concat depth
#define BM    64        // rows per CTA
#define NCTA  (BB/BM)   // 128
#define EPSV  1e-5f
#define SG_STRIDE 514   // gates smem row stride (floats), even for 8B stores

// ------------------------- device scratch (no mallocs) ---------------------
__device__ float d_mom[TT * 5];                       // per-t input moments
__device__ float d_A[TT * EE], d_Bc[TT * EE], d_Cc[TT * EE];
__device__ __align__(256) float d_Wt[KTOT * GG];      // [k][n] fused weights
__device__ float d_bias[GG];                          // b_ih + b_hh
__device__ float d_Y[(size_t)TT * BB * DOUT];         // pre-BN outputs [t][b][o]

// ------------------------- helpers -----------------------------------------
__device__ __forceinline__ void ffma2(unsigned long long& d,
                                      unsigned long long a,
                                      unsigned long long b) {
    asm volatile("fma.rn.f32x2 %0, %1, %2, %0;" : "+l"(d) : "l"(a), "l"(b));
}
__device__ __forceinline__ unsigned long long dup2(float x) {
    unsigned long long r;
    unsigned int xi = __float_as_uint(x);
    asm("mov.b64 %0, {%1, %1};" : "=l"(r) : "r"(xi));
    return r;
}
__device__ __forceinline__ float sigm(float x) {
    return 1.0f / (1.0f + expf(-x));
}

// ------------------------- K1: input moments per t --------------------------
__global__ void k_moments(const float* __restrict__ inp) {
    int t = blockIdx.x, tid = threadIdx.x;
    float su = 0.f, sv = 0.f, suu = 0.f, svv = 0.f, suv = 0.f;
    for (int b = tid; b < BB; b += 256) {
        float2 uv = *(const float2*)(inp + ((size_t)b * TT + t) * 2);
        su += uv.x; sv += uv.y;
        suu += uv.x * uv.x; svv += uv.y * uv.y; suv += uv.x * uv.y;
    }
    __shared__ float red[5][256];
    red[0][tid] = su; red[1][tid] = sv; red[2][tid] = suu;
    red[3][tid] = svv; red[4][tid] = suv;
    __syncthreads();
    for (int s = 128; s > 0; s >>= 1) {
        if (tid < s) {
            #pragma unroll
            for (int m = 0; m < 5; m++) red[m][tid] += red[m][tid + s];
        }
        __syncthreads();
    }
    if (tid < 5) d_mom[t * 5 + tid] = red[tid][0] * (1.0f / BB);
}

// ------------------ K2: BN coeffs + weight transpose + bias -----------------
__global__ void k_prep(const float* __restrict__ W_emb, const float* __restrict__ b_emb,
                       const float* __restrict__ g_emb, const float* __restrict__ be_emb,
                       const float* __restrict__ W_ih, const float* __restrict__ W_hh,
                       const float* __restrict__ b_ih, const float* __restrict__ b_hh) {
    int idx = blockIdx.x * 256 + threadIdx.x;   // grid covers 131072
    if (idx < KTOT * GG) {
        int k = idx / GG, n = idx % GG;
        d_Wt[idx] = (k < CC) ? W_ih[n * CC + k] : W_hh[n * CC + (k - CC)];
    }
    if (idx < GG) d_bias[idx] = b_ih[idx] + b_hh[idx];
    if (idx < TT * EE) {
        int t = idx >> 7, e = idx & 127;
        float w0 = W_emb[e * 2], w1 = W_emb[e * 2 + 1], bb = b_emb[e];
        float mu_u = d_mom[t * 5 + 0], mu_v = d_mom[t * 5 + 1];
        float vu  = d_mom[t * 5 + 2] - mu_u * mu_u;
        float vv  = d_mom[t * 5 + 3] - mu_v * mu_v;
        float cuv = d_mom[t * 5 + 4] - mu_u * mu_v;
        float mu  = w0 * mu_u + w1 * mu_v + bb;
        float var = w0 * w0 * vu + w1 * w1 * vv + 2.f * w0 * w1 * cuv;
        float sc  = g_emb[e] * rsqrtf(var + EPSV);
        d_A[idx]  = sc * w0;
        d_Bc[idx] = sc * w1;
        d_Cc[idx] = sc * (bb - mu) + be_emb[e];
    }
}

// ------------------------- K3: persistent LSTM ------------------------------
// dynamic smem layout: sC[KTOT][BM] (concat^T: xbn rows 0..127, h rows 128..255)
//                      sG[BM][SG_STRIDE] (gates)
__global__ void __launch_bounds__(256, 1)
k_lstm(const float* __restrict__ inp,
       const float* __restrict__ W_out, const float* __restrict__ b_out) {
    extern __shared__ float smem[];
    float* sC = smem;                 // KTOT*BM floats = 64 KB
    float* sG = smem + KTOT * BM;     // BM*SG_STRIDE floats = 128.5 KB

    __shared__ float sWout[DOUT * CC];
    __shared__ float sBias[GG];
    __shared__ float sUV[BM][2];
    __shared__ float sYred[4][BM][DOUT];

    const int tid  = threadIdx.x;
    const int lane = tid & 31;
    const int wid  = tid >> 5;
    const int b0   = blockIdx.x * BM;

    for (int i = tid; i < DOUT * CC; i += 256) sWout[i] = W_out[i];
    for (int i = tid; i < GG; i += 256)        sBias[i] = d_bias[i];
    for (int i = tid; i < CC * BM; i += 256)   sC[CC * BM + i] = 0.f;  // h0 = 0

    float c_reg[32];
    #pragma unroll
    for (int j = 0; j < 32; j++) c_reg[j] = 0.f;
    __syncthreads();

    const int rowE = tid & 63;   // elementwise: this thread's row
    const int qE   = tid >> 6;   // 0..3: n residue class

    for (int t = 0; t < TT; t++) {
        // ---- stage per-row inputs (u,v) for this step ----
        if (tid < BM) {
            float2 uv = *(const float2*)(inp + ((size_t)(b0 + tid) * TT + t) * 2);
            sUV[tid][0] = uv.x;
            sUV[tid][1] = uv.y;
        }
        __syncthreads();

        // ---- xbn fill: sC[e][row] = relu(a*u + b*v + c) ----
        const float* Ar = d_A  + t * EE;
        const float* Br = d_Bc + t * EE;
        const float* Cr = d_Cc + t * EE;
        for (int idx = tid; idx < EE * BM; idx += 256) {
            int e = idx >> 6, row = idx & 63;
            float x = fmaf(Ar[e], sUV[row][0], fmaf(Br[e], sUV[row][1], Cr[e]));
            sC[e * BM + row] = fmaxf(x, 0.f);
        }
        __syncthreads();

        // ---- gates GEMM: 64 x 512, K=256, f32x2 packed ----
        // thread tile: rows wid*8..+8, col pairs {lane*2+64j, +1}, j=0..7
        unsigned long long acc[8][8];
        #pragma unroll
        for (int i = 0; i < 8; i++)
            #pragma unroll
            for (int j = 0; j < 8; j++) acc[i][j] = 0ULL;

        const float* crow = sC + wid * 8;
        #pragma unroll 2
        for (int k = 0; k < KTOT; k++) {
            const unsigned long long* wr =
                (const unsigned long long*)(d_Wt + (size_t)k * GG) + lane;
            unsigned long long w[8];
            #pragma unroll
            for (int j = 0; j < 8; j++) w[j] = wr[32 * j];

            const float4* c4 = (const float4*)(crow + k * BM);
            float4 ra = c4[0], rb = c4[1];
            unsigned long long rp[8];
            rp[0] = dup2(ra.x); rp[1] = dup2(ra.y);
            rp[2] = dup2(ra.z); rp[3] = dup2(ra.w);
            rp[4] = dup2(rb.x); rp[5] = dup2(rb.y);
            rp[6] = dup2(rb.z); rp[7] = dup2(rb.w);

            #pragma unroll
            for (int i = 0; i < 8; i++)
                #pragma unroll
                for (int j = 0; j < 8; j++) ffma2(acc[i][j], w[j], rp[i]);
        }

        // ---- writeback gates to smem (contiguous 8B stores, conflict-free) ----
        #pragma unroll
        for (int i = 0; i < 8; i++) {
            float* gr = sG + (wid * 8 + i) * SG_STRIDE + lane * 2;
            #pragma unroll
            for (int j = 0; j < 8; j++)
                *(unsigned long long*)(gr + 64 * j) = acc[i][j];
        }
        __syncthreads();

        // ---- LSTM cell elementwise + y partials ----
        float ypart[DOUT];
        #pragma unroll
        for (int o = 0; o < DOUT; o++) ypart[o] = 0.f;

        const float* grow = sG + rowE * SG_STRIDE;
        #pragma unroll
        for (int j = 0; j < 32; j++) {
            int n = qE + 4 * j;
            float gi = grow[n]          + sBias[n];
            float gf = grow[CC + n]     + sBias[CC + n];
            float gg = grow[2 * CC + n] + sBias[2 * CC + n];
            float go = grow[3 * CC + n] + sBias[3 * CC + n];
            float si = sigm(gi), sf = sigm(gf), so = sigm(go);
            float tg = tanhf(gg);
            float cn = sf * c_reg[j] + si * tg;
            c_reg[j] = cn;
            float h = so * tanhf(cn);
            sC[(CC + n) * BM + rowE] = h;          // h for next step's GEMM
            #pragma unroll
            for (int o = 0; o < DOUT; o++)
                ypart[o] = fmaf(h, sWout[o * CC + n], ypart[o]);
        }
        #pragma unroll
        for (int o = 0; o < DOUT; o++) sYred[qE][rowE][o] = ypart[o];
        __syncthreads();

        // ---- combine y partials, write scratch Y ----
        for (int ii = tid; ii < BM * DOUT; ii += 256) {
            int row = ii / DOUT, o = ii % DOUT;
            float y = sYred[0][row][o] + sYred[1][row][o] +
                      sYred[2][row][o] + sYred[3][row][o] + b_out[o];
            d_Y[((size_t)t * BB + b0 + row) * DOUT + o] = y;
        }
        __syncthreads();
    }
}

// ------------------------- K4: output BN + ReLU + transpose -----------------
__global__ void k_final(const float* __restrict__ g_out,
                        const float* __restrict__ be_out,
                        float* __restrict__ out) {
    int t = blockIdx.x, tid = threadIdx.x;
    float s1[DOUT], s2[DOUT];
    #pragma unroll
    for (int o = 0; o < DOUT; o++) { s1[o] = 0.f; s2[o] = 0.f; }
    for (int b = tid; b < BB; b += 256) {
        const float* y = d_Y + ((size_t)t * BB + b) * DOUT;
        #pragma unroll
        for (int o = 0; o < DOUT; o++) { float v = y[o]; s1[o] += v; s2[o] += v * v; }
    }
    __shared__ float r1[DOUT][256], r2[DOUT][256];
    #pragma unroll
    for (int o = 0; o < DOUT; o++) { r1[o][tid] = s1[o]; r2[o][tid] = s2[o]; }
    __syncthreads();
    for (int s = 128; s > 0; s >>= 1) {
        if (tid < s) {
            #pragma unroll
            for (int o = 0; o < DOUT; o++) {
                r1[o][tid] += r1[o][tid + s];
                r2[o][tid] += r2[o][tid + s];
            }
        }
        __syncthreads();
    }
    __shared__ float mu[DOUT], rs[DOUT], bb[DOUT];
    if (tid < DOUT) {
        float m = r1[tid][0] * (1.0f / BB);
        float v = r2[tid][0] * (1.0f / BB) - m * m;
        mu[tid] = m;
        rs[tid] = rsqrtf(v + EPSV) * g_out[tid];
        bb[tid] = be_out[tid];
    }
    __syncthreads();
    for (int b = tid; b < BB; b += 256) {
        const float* y = d_Y + ((size_t)t * BB + b) * DOUT;
        float* op = out + ((size_t)b * TT + t) * DOUT;
        #pragma unroll
        for (int o = 0; o < DOUT; o++)
            op[o] = fmaxf(fmaf(y[o] - mu[o], rs[o], bb[o]), 0.f);
    }
}

// ------------------------- launch -------------------------------------------
extern "C" void kernel_launch(void* const* d_in, const int* in_sizes, int n_in,
                              void* d_out, int out_size) {
    const float* inp    = (const float*)d_in[0];
    const float* W_emb  = (const float*)d_in[1];
    const float* b_emb  = (const float*)d_in[2];
    const float* g_emb  = (const float*)d_in[3];
    const float* be_emb = (const float*)d_in[4];
    const float* W_ih   = (const float*)d_in[5];
    const float* W_hh   = (const float*)d_in[6];
    const float* b_ih   = (const float*)d_in[7];
    const float* b_hh   = (const float*)d_in[8];
    const float* W_out  = (const float*)d_in[9];
    const float* b_out  = (const float*)d_in[10];
    const float* g_out  = (const float*)d_in[11];
    const float* be_out = (const float*)d_in[12];
    float* out = (float*)d_out;

    const int lstm_smem = (KTOT * BM + BM * SG_STRIDE) * (int)sizeof(float); // 197120
    cudaFuncSetAttribute(k_lstm, cudaFuncAttributeMaxDynamicSharedMemorySize, lstm_smem);

    k_moments<<<TT, 256>>>(inp);
    k_prep<<<512, 256>>>(W_emb, b_emb, g_emb, be_emb, W_ih, W_hh, b_ih, b_hh);
    k_lstm<<<NCTA, 256, lstm_smem>>>(inp, W_out, b_out);
    k_final<<<TT, 256>>>(g_out, be_out, out);
}

// round 4
// speedup vs baseline: 1.4852x; 1.4852x over previous
#include <cuda_runtime.h>

// ---------------------------------------------------------------------------
// VanillaLSTM on GB300 — R3: R2 design + k_out smem-load fix.
// Persistent fp32 LSTM, f32x2 FMA, cp.async double-buffered weight streaming,
// register-resident cell update. B=8192, T=128, E=C=128, G=512, Dout=5.
// ---------------------------------------------------------------------------

#define BB    8192
#define TT    128
#define EE    128
#define CC    128
#define GG    512
#define DOUT  5
#define KTOT  256
#define BM    64
#define NCTA  (BB/BM)
#define EPSV  1e-5f
#define SC_STR 66            // sC row stride (floats): 8B-aligned, breaks conflicts
#define CK    32             // k-rows per weight chunk
#define NCHUNK (KTOT/CK)     // 8
#define WCH   (CK*GG)        // floats per chunk buffer (64KB)

// ------------------------- device scratch ----------------------------------
__device__ float d_mom[TT * 5];
__device__ float d_A[TT * EE], d_Bc[TT * EE], d_Cc[TT * EE];
__device__ __align__(256) float d_Wt[KTOT * GG];
__device__ float d_bias[GG];
__device__ float d_H[(size_t)TT * BB * CC];     // h for all steps [t][b][c]
__device__ float d_Y[(size_t)TT * BB * DOUT];   // pre-BN outputs [t][b][o]

typedef unsigned long long ull;

// ------------------------- helpers -----------------------------------------
__device__ __forceinline__ void ffma2(ull& d, ull a, ull b) {
    asm("fma.rn.f32x2 %0, %1, %2, %0;" : "+l"(d) : "l"(a), "l"(b));
}
__device__ __forceinline__ ull dup2(float x) {
    ull r; unsigned xi = __float_as_uint(x);
    asm("mov.b64 %0, {%1, %1};" : "=l"(r) : "r"(xi));
    return r;
}
__device__ __forceinline__ float2 unpk(ull v) {
    float2 r;
    asm("mov.b64 {%0, %1}, %2;" : "=f"(r.x), "=f"(r.y) : "l"(v));
    return r;
}
__device__ __forceinline__ ull pk2(float x, float y) {
    ull r;
    asm("mov.b64 %0, {%1, %2};" : "=l"(r) : "f"(x), "f"(y));
    return r;
}
__device__ __forceinline__ void cpa16(float* dst, const float* src) {
    unsigned s = (unsigned)__cvta_generic_to_shared(dst);
    asm volatile("cp.async.cg.shared.global [%0], [%1], 16;" :: "r"(s), "l"(src));
}
__device__ __forceinline__ float sigm(float x) {
    return __fdividef(1.f, 1.f + __expf(-x));
}
__device__ __forceinline__ float tanh_f(float x) {
    return 1.f - __fdividef(2.f, __expf(2.f * x) + 1.f);
}

// ------------------------- K1: input moments per t --------------------------
__global__ void k_moments(const float* __restrict__ inp) {
    int t = blockIdx.x, tid = threadIdx.x;
    float su = 0.f, sv = 0.f, suu = 0.f, svv = 0.f, suv = 0.f;
    for (int b = tid; b < BB; b += 256) {
        float2 uv = *(const float2*)(inp + ((size_t)b * TT + t) * 2);
        su += uv.x; sv += uv.y;
        suu += uv.x * uv.x; svv += uv.y * uv.y; suv += uv.x * uv.y;
    }
    __shared__ float red[5][256];
    red[0][tid] = su; red[1][tid] = sv; red[2][tid] = suu;
    red[3][tid] = svv; red[4][tid] = suv;
    __syncthreads();
    for (int s = 128; s > 0; s >>= 1) {
        if (tid < s) {
            #pragma unroll
            for (int m = 0; m < 5; m++) red[m][tid] += red[m][tid + s];
        }
        __syncthreads();
    }
    if (tid < 5) d_mom[t * 5 + tid] = red[tid][0] * (1.0f / BB);
}

// ------------------ K2: BN coeffs + weight transpose + bias -----------------
__global__ void k_prep(const float* __restrict__ W_emb, const float* __restrict__ b_emb,
                       const float* __restrict__ g_emb, const float* __restrict__ be_emb,
                       const float* __restrict__ W_ih, const float* __restrict__ W_hh,
                       const float* __restrict__ b_ih, const float* __restrict__ b_hh) {
    int idx = blockIdx.x * 256 + threadIdx.x;
    if (idx < KTOT * GG) {
        int k = idx / GG, n = idx % GG;
        d_Wt[idx] = (k < CC) ? W_ih[n * CC + k] : W_hh[n * CC + (k - CC)];
    }
    if (idx < GG) d_bias[idx] = b_ih[idx] + b_hh[idx];
    if (idx < TT * EE) {
        int t = idx >> 7, e = idx & 127;
        float w0 = W_emb[e * 2], w1 = W_emb[e * 2 + 1], bb = b_emb[e];
        float mu_u = d_mom[t * 5 + 0], mu_v = d_mom[t * 5 + 1];
        float vu  = d_mom[t * 5 + 2] - mu_u * mu_u;
        float vv  = d_mom[t * 5 + 3] - mu_v * mu_v;
        float cuv = d_mom[t * 5 + 4] - mu_u * mu_v;
        float mu  = w0 * mu_u + w1 * mu_v + bb;
        float var = w0 * w0 * vu + w1 * w1 * vv + 2.f * w0 * w1 * cuv;
        float sc  = g_emb[e] * rsqrtf(var + EPSV);
        d_A[idx]  = sc * w0;
        d_Bc[idx] = sc * w1;
        d_Cc[idx] = sc * (bb - mu) + be_emb[e];
    }
}

// ------------------------- K3: persistent LSTM ------------------------------
// dyn smem: sC[KTOT][SC_STR] (xbn rows 0..127, h rows 128..255) = 67.6KB
//           sW: 2 x WCH weight chunk buffers = 128KB
__global__ void __launch_bounds__(256, 1)
k_lstm(const float* __restrict__ inp) {
    extern __shared__ float smem[];
    float* sC = smem;                       // KTOT * SC_STR
    float* sW = smem + KTOT * SC_STR;       // 2 * WCH

    __shared__ float sBias[GG];
    __shared__ float sUV[BM * 2];
    __shared__ float sAe[EE], sBe[EE], sCe[EE];

    const int tid  = threadIdx.x;
    const int lane = tid & 31;
    const int wid  = tid >> 5;
    const int b0   = blockIdx.x * BM;

    for (int i = tid; i < GG; i += 256) sBias[i] = d_bias[i];
    for (int i = tid; i < CC * BM; i += 256) {
        int k = CC + (i >> 6), r = i & 63;
        sC[k * SC_STR + r] = 0.f;           // h0 = 0
    }

    // prologue: stage chunk 0 into buf0
    for (int i = tid; i < WCH / 4; i += 256) cpa16(sW + i * 4, d_Wt + i * 4);
    asm volatile("cp.async.commit_group;");

    float cst[32];
    #pragma unroll
    for (int i = 0; i < 32; i++) cst[i] = 0.f;

    const int nA = 2 * lane;
    const int nB = 64 + 2 * lane;

    for (int t = 0; t < TT; t++) {
        __syncthreads();   // prev step's h writes done; sAe safe to overwrite
        if (tid < BM) {
            float2 uv = *(const float2*)(inp + ((size_t)(b0 + tid) * TT + t) * 2);
            sUV[tid * 2]     = uv.x;
            sUV[tid * 2 + 1] = uv.y;
        }
        if (tid < EE) {
            sAe[tid] = d_A[t * EE + tid];
            sBe[tid] = d_Bc[t * EE + tid];
            sCe[tid] = d_Cc[t * EE + tid];
        }
        __syncthreads();

        // xbn fill: sC[e][row] = relu(a*u + b*v + c)
        for (int idx = tid; idx < EE * BM; idx += 256) {
            int e = idx >> 6, r = idx & 63;
            float x = fmaf(sAe[e], sUV[r * 2], fmaf(sBe[e], sUV[r * 2 + 1], sCe[e]));
            sC[e * SC_STR + r] = fmaxf(x, 0.f);
        }

        // ---- gates GEMM: 64x512, K=256, pipelined weight chunks ----
        ull acc[8][8];
        #pragma unroll
        for (int i = 0; i < 8; i++)
            #pragma unroll
            for (int j = 0; j < 8; j++) acc[i][j] = 0ULL;

        for (int c = 0; c < NCHUNK; c++) {
            asm volatile("cp.async.wait_group 0;" ::: "memory");
            __syncthreads();   // chunk c data visible; prior chunk's readers done
            {   // prefetch next chunk (wraps to chunk 0 for next t)
                int nc = (c + 1) & (NCHUNK - 1);
                float* dst = sW + ((c + 1) & 1) * WCH;
                const float* src = d_Wt + nc * WCH;
                for (int i = tid; i < WCH / 4; i += 256) cpa16(dst + i * 4, src + i * 4);
                asm volatile("cp.async.commit_group;");
            }
            const float* buf   = sW + (c & 1) * WCH;
            const float* crow0 = sC + (c * CK) * SC_STR + wid * 8;
            #pragma unroll 4
            for (int kk = 0; kk < CK; kk++) {
                const ull* wr = (const ull*)(buf + kk * GG) + lane;
                ull w[8];
                #pragma unroll
                for (int j = 0; j < 8; j++) w[j] = wr[32 * j];

                const ull* c2 = (const ull*)(crow0 + kk * SC_STR);
                float2 f0 = unpk(c2[0]), f1 = unpk(c2[1]);
                float2 f2 = unpk(c2[2]), f3 = unpk(c2[3]);
                ull rp[8];
                rp[0] = dup2(f0.x); rp[1] = dup2(f0.y);
                rp[2] = dup2(f1.x); rp[3] = dup2(f1.y);
                rp[4] = dup2(f2.x); rp[5] = dup2(f2.y);
                rp[6] = dup2(f3.x); rp[7] = dup2(f3.y);

                #pragma unroll
                for (int i = 0; i < 8; i++)
                    #pragma unroll
                    for (int j = 0; j < 8; j++) ffma2(acc[i][j], w[j], rp[i]);
            }
        }
        __syncthreads();   // all warps done reading sC h region

        // ---- cell update in registers; thread owns gate quadruples ----
        // pair A: n in {nA, nA+1} -> acc[i][0](i) [2](f) [4](g) [6](o)
        // pair B: n in {nB, nB+1} -> acc[i][1]    [3]    [5]    [7]
        float* Hbase = d_H + (size_t)t * BB * CC + (size_t)b0 * CC;
        const float biA0 = sBias[nA],          biA1 = sBias[nA + 1];
        const float bfA0 = sBias[CC + nA],     bfA1 = sBias[CC + nA + 1];
        const float bgA0 = sBias[2*CC + nA],   bgA1 = sBias[2*CC + nA + 1];
        const float boA0 = sBias[3*CC + nA],   boA1 = sBias[3*CC + nA + 1];
        const float biB0 = sBias[nB],          biB1 = sBias[nB + 1];
        const float bfB0 = sBias[CC + nB],     bfB1 = sBias[CC + nB + 1];
        const float bgB0 = sBias[2*CC + nB],   bgB1 = sBias[2*CC + nB + 1];
        const float boB0 = sBias[3*CC + nB],   boB1 = sBias[3*CC + nB + 1];

        #pragma unroll
        for (int i = 0; i < 8; i++) {
            const int row = wid * 8 + i;
            // pair A
            {
                float2 gi = unpk(acc[i][0]), gf = unpk(acc[i][2]);
                float2 gg = unpk(acc[i][4]), go = unpk(acc[i][6]);
                float i0 = sigm(gi.x + biA0), f0v = sigm(gf.x + bfA0);
                float g0 = tanh_f(gg.x + bgA0), o0 = sigm(go.x + boA0);
                float c0 = f0v * cst[i*4+0] + i0 * g0; cst[i*4+0] = c0;
                float h0 = o0 * tanh_f(c0);
                float i1 = sigm(gi.y + biA1), f1v = sigm(gf.y + bfA1);
                float g1 = tanh_f(gg.y + bgA1), o1 = sigm(go.y + boA1);
                float c1 = f1v * cst[i*4+1] + i1 * g1; cst[i*4+1] = c1;
                float h1 = o1 * tanh_f(c1);
                sC[(CC + nA)     * SC_STR + row] = h0;
                sC[(CC + nA + 1) * SC_STR + row] = h1;
                *(ull*)(Hbase + (size_t)row * CC + nA) = pk2(h0, h1);
            }
            // pair B
            {
                float2 gi = unpk(acc[i][1]), gf = unpk(acc[i][3]);
                float2 gg = unpk(acc[i][5]), go = unpk(acc[i][7]);
                float i0 = sigm(gi.x + biB0), f0v = sigm(gf.x + bfB0);
                float g0 = tanh_f(gg.x + bgB0), o0 = sigm(go.x + boB0);
                float c0 = f0v * cst[i*4+2] + i0 * g0; cst[i*4+2] = c0;
                float h0 = o0 * tanh_f(c0);
                float i1 = sigm(gi.y + biB1), f1v = sigm(gf.y + bfB1);
                float g1 = tanh_f(gg.y + bgB1), o1 = sigm(go.y + boB1);
                float c1 = f1v * cst[i*4+3] + i1 * g1; cst[i*4+3] = c1;
                float h1 = o1 * tanh_f(c1);
                sC[(CC + nB)     * SC_STR + row] = h0;
                sC[(CC + nB + 1) * SC_STR + row] = h1;
                *(ull*)(Hbase + (size_t)row * CC + nB) = pk2(h0, h1);
            }
        }
    }
}

// ------------------------- K4: output head y = h@Wout^T + b -----------------
__global__ void k_out(const float* __restrict__ W_out, const float* __restrict__ b_out) {
    __shared__ float sW[DOUT * CC];
    __shared__ float sb[DOUT];
    int tid = threadIdx.x;
    for (int i = tid; i < DOUT * CC; i += 256) sW[i] = W_out[i];   // FIX: full 640
    if (tid < DOUT) sb[tid] = b_out[tid];
    __syncthreads();
    size_t g = (size_t)blockIdx.x * 256 + tid;     // over TT*BB
    const float4* h4 = (const float4*)(d_H + g * CC);
    float y0 = sb[0], y1 = sb[1], y2 = sb[2], y3 = sb[3], y4 = sb[4];
    #pragma unroll 8
    for (int c = 0; c < CC / 4; c++) {
        float4 h = h4[c];
        const float4* w4 = (const float4*)sW + c;
        float4 a = w4[0], b = w4[32], d = w4[64], e = w4[96], f = w4[128];
        y0 += h.x * a.x + h.y * a.y + h.z * a.z + h.w * a.w;
        y1 += h.x * b.x + h.y * b.y + h.z * b.z + h.w * b.w;
        y2 += h.x * d.x + h.y * d.y + h.z * d.z + h.w * d.w;
        y3 += h.x * e.x + h.y * e.y + h.z * e.z + h.w * e.w;
        y4 += h.x * f.x + h.y * f.y + h.z * f.z + h.w * f.w;
    }
    float* yo = d_Y + g * DOUT;
    yo[0] = y0; yo[1] = y1; yo[2] = y2; yo[3] = y3; yo[4] = y4;
}

// ------------------------- K5: output BN + ReLU + transpose -----------------
__global__ void k_final(const float* __restrict__ g_out,
                        const float* __restrict__ be_out,
                        float* __restrict__ out) {
    int t = blockIdx.x, tid = threadIdx.x;
    float s1[DOUT], s2[DOUT];
    #pragma unroll
    for (int o = 0; o < DOUT; o++) { s1[o] = 0.f; s2[o] = 0.f; }
    for (int b = tid; b < BB; b += 256) {
        const float* y = d_Y + ((size_t)t * BB + b) * DOUT;
        #pragma unroll
        for (int o = 0; o < DOUT; o++) { float v = y[o]; s1[o] += v; s2[o] += v * v; }
    }
    __shared__ float r1[DOUT][256], r2[DOUT][256];
    #pragma unroll
    for (int o = 0; o < DOUT; o++) { r1[o][tid] = s1[o]; r2[o][tid] = s2[o]; }
    __syncthreads();
    for (int s = 128; s > 0; s >>= 1) {
        if (tid < s) {
            #pragma unroll
            for (int o = 0; o < DOUT; o++) {
                r1[o][tid] += r1[o][tid + s];
                r2[o][tid] += r2[o][tid + s];
            }
        }
        __syncthreads();
    }
    __shared__ float mu[DOUT], rs[DOUT], bb[DOUT];
    if (tid < DOUT) {
        float m = r1[tid][0] * (1.0f / BB);
        float v = r2[tid][0] * (1.0f / BB) - m * m;
        mu[tid] = m;
        rs[tid] = rsqrtf(v + EPSV) * g_out[tid];
        bb[tid] = be_out[tid];
    }
    __syncthreads();
    for (int b = tid; b < BB; b += 256) {
        const float* y = d_Y + ((size_t)t * BB + b) * DOUT;
        float* op = out + ((size_t)b * TT + t) * DOUT;
        #pragma unroll
        for (int o = 0; o < DOUT; o++)
            op[o] = fmaxf(fmaf(y[o] - mu[o], rs[o], bb[o]), 0.f);
    }
}

// ------------------------- launch -------------------------------------------
extern "C" void kernel_launch(void* const* d_in, const int* in_sizes, int n_in,
                              void* d_out, int out_size) {
    const float* inp    = (const float*)d_in[0];
    const float* W_emb  = (const float*)d_in[1];
    const float* b_emb  = (const float*)d_in[2];
    const float* g_emb  = (const float*)d_in[3];
    const float* be_emb = (const float*)d_in[4];
    const float* W_ih   = (const float*)d_in[5];
    const float* W_hh   = (const float*)d_in[6];
    const float* b_ih   = (const float*)d_in[7];
    const float* b_hh   = (const float*)d_in[8];
    const float* W_out  = (const float*)d_in[9];
    const float* b_out  = (const float*)d_in[10];
    const float* g_out  = (const float*)d_in[11];
    const float* be_out = (const float*)d_in[12];
    float* out = (float*)d_out;

    const int lstm_smem = (KTOT * SC_STR + 2 * WCH) * (int)sizeof(float); // 198656
    cudaFuncSetAttribute(k_lstm, cudaFuncAttributeMaxDynamicSharedMemorySize, lstm_smem);

    k_moments<<<TT, 256>>>(inp);
    k_prep<<<512, 256>>>(W_emb, b_emb, g_emb, be_emb, W_ih, W_hh, b_ih, b_hh);
    k_lstm<<<NCTA, 256, lstm_smem>>>(inp);
    k_out<<<(TT * BB) / 256, 256>>>(W_out, b_out);
    k_final<<<TT, 256>>>(g_out, be_out, out);
}